// round 2
// baseline (speedup 1.0000x reference)
#include <cuda_runtime.h>

// Problem geometry (fixed by the dataset)
constexpr int Bn = 16;
constexpr int Hh = 352;
constexpr int Ww = 1216;
constexpr int HW = Hh * Ww;          // 428032
constexpr long long NT = (long long)Bn * HW;
constexpr int QPI = HW / 4;          // quads per image = 107008 = 418*256 exactly
constexpr int BLK = 256;
constexpr int GRIDX = QPI / BLK;     // 418

// Scratch (allocation-free rule: __device__ globals)
__device__ float  g_pc[NT];
__device__ float  g_tc[NT];
__device__ double g_sums[Bn][3];     // [img][0]=sum(mask) [1]=sum(m*|pc|) [2]=sum(m*|tc|)
__device__ double g_loss;

__global__ void k_init() {
    int i = threadIdx.x;
    if (i < Bn) { g_sums[i][0] = 0.0; g_sums[i][1] = 0.0; g_sums[i][2] = 0.0; }
    if (i == 0) g_loss = 0.0;
}

__device__ __forceinline__ void sort3(float& a, float& b, float& c) {
    float t;
    t = fminf(a, b); b = fmaxf(a, b); a = t;
    t = fminf(a, c); c = fmaxf(a, c); a = t;
    t = fminf(b, c); c = fmaxf(b, c); b = t;
}
__device__ __forceinline__ float med3(float a, float b, float c) {
    return fmaxf(fminf(a, b), fminf(fmaxf(a, b), c));
}
__device__ __forceinline__ float max3(float a, float b, float c) { return fmaxf(a, fmaxf(b, c)); }
__device__ __forceinline__ float min3(float a, float b, float c) { return fminf(a, fminf(b, c)); }

__device__ __forceinline__ float warp_sum(float v) {
    #pragma unroll
    for (int o = 16; o; o >>= 1) v += __shfl_down_sync(0xffffffffu, v, o);
    return v;
}

// pass1: compute contrasts (3x3 lower median, zero pad), store them, accumulate per-image sums.
// Each thread handles 4 horizontal pixels [x4, x4+3].
__global__ __launch_bounds__(BLK) void k_pass1(const float* __restrict__ pred,
                                               const float* __restrict__ targ,
                                               const float* __restrict__ mask) {
    int img = blockIdx.y;
    int q   = blockIdx.x * BLK + threadIdx.x;   // quad index, always < QPI (exact tiling)
    int y   = q / (Ww / 4);
    int x4  = (q % (Ww / 4)) * 4;

    const float* pb = pred + (long long)img * HW;
    const float* tb = targ + (long long)img * HW;

    // 3 rows x 6 cols windows (cols x4-1 .. x4+4), zero padded
    float pr[3][6], tr[3][6];
    #pragma unroll
    for (int r = 0; r < 3; r++) {
        int yy = y + r - 1;
        if (yy < 0 || yy >= Hh) {
            #pragma unroll
            for (int c = 0; c < 6; c++) { pr[r][c] = 0.f; tr[r][c] = 0.f; }
        } else {
            const float* prow = pb + (long long)yy * Ww;
            const float* trow = tb + (long long)yy * Ww;
            float4 pv = *reinterpret_cast<const float4*>(prow + x4);
            float4 tv = *reinterpret_cast<const float4*>(trow + x4);
            pr[r][1] = pv.x; pr[r][2] = pv.y; pr[r][3] = pv.z; pr[r][4] = pv.w;
            tr[r][1] = tv.x; tr[r][2] = tv.y; tr[r][3] = tv.z; tr[r][4] = tv.w;
            pr[r][0] = (x4 > 0)        ? __ldg(prow + x4 - 1) : 0.f;
            pr[r][5] = (x4 + 4 < Ww)   ? __ldg(prow + x4 + 4) : 0.f;
            tr[r][0] = (x4 > 0)        ? __ldg(trow + x4 - 1) : 0.f;
            tr[r][5] = (x4 + 4 < Ww)   ? __ldg(trow + x4 + 4) : 0.f;
        }
    }

    // column-sorted triples for both tensors
    float plo[6], pmi[6], phi[6], tlo[6], tmi[6], thi[6];
    #pragma unroll
    for (int c = 0; c < 6; c++) {
        float a = pr[0][c], b = pr[1][c], d = pr[2][c];
        sort3(a, b, d); plo[c] = a; pmi[c] = b; phi[c] = d;
        a = tr[0][c]; b = tr[1][c]; d = tr[2][c];
        sort3(a, b, d); tlo[c] = a; tmi[c] = b; thi[c] = d;
    }

    float pcs[4], tcs[4];
    #pragma unroll
    for (int i = 0; i < 4; i++) {
        float mp = med3(max3(plo[i], plo[i+1], plo[i+2]),
                        med3(pmi[i], pmi[i+1], pmi[i+2]),
                        min3(phi[i], phi[i+1], phi[i+2]));
        float mt = med3(max3(tlo[i], tlo[i+1], tlo[i+2]),
                        med3(tmi[i], tmi[i+1], tmi[i+2]),
                        min3(thi[i], thi[i+1], thi[i+2]));
        pcs[i] = pr[1][i+1] - mp;
        tcs[i] = tr[1][i+1] - mt;
    }

    long long base = (long long)img * HW + (long long)y * Ww + x4;
    *reinterpret_cast<float4*>(g_pc + base) = make_float4(pcs[0], pcs[1], pcs[2], pcs[3]);
    *reinterpret_cast<float4*>(g_tc + base) = make_float4(tcs[0], tcs[1], tcs[2], tcs[3]);

    float4 mv = *reinterpret_cast<const float4*>(mask + base);
    float sm = mv.x + mv.y + mv.z + mv.w;
    float sp = mv.x * fabsf(pcs[0]) + mv.y * fabsf(pcs[1]) + mv.z * fabsf(pcs[2]) + mv.w * fabsf(pcs[3]);
    float st = mv.x * fabsf(tcs[0]) + mv.y * fabsf(tcs[1]) + mv.z * fabsf(tcs[2]) + mv.w * fabsf(tcs[3]);

    // block reduce 3 values
    __shared__ float sh[8][3];
    int lane = threadIdx.x & 31, w = threadIdx.x >> 5;
    sm = warp_sum(sm); sp = warp_sum(sp); st = warp_sum(st);
    if (lane == 0) { sh[w][0] = sm; sh[w][1] = sp; sh[w][2] = st; }
    __syncthreads();
    if (w == 0) {
        sm = (lane < 8) ? sh[lane][0] : 0.f;
        sp = (lane < 8) ? sh[lane][1] : 0.f;
        st = (lane < 8) ? sh[lane][2] : 0.f;
        sm = warp_sum(sm); sp = warp_sum(sp); st = warp_sum(st);
        if (lane == 0) {
            atomicAdd(&g_sums[img][0], (double)sm);
            atomicAdd(&g_sums[img][1], (double)sp);
            atomicAdd(&g_sums[img][2], (double)st);
        }
    }
}

// pass2: stream contrasts, accumulate sum |pc/mean_p - tc/mean_t|
__global__ __launch_bounds__(BLK) void k_pass2() {
    int img = blockIdx.y;
    int q   = blockIdx.x * BLK + threadIdx.x;

    double denom = g_sums[img][0];
    float fp = (float)(denom / g_sums[img][1]);   // 1/mean_pred
    float ft = (float)(denom / g_sums[img][2]);   // 1/mean_target

    long long base = (long long)img * HW + (long long)q * 4;
    float4 p = *reinterpret_cast<const float4*>(g_pc + base);
    float4 t = *reinterpret_cast<const float4*>(g_tc + base);
    float acc = fabsf(p.x * fp - t.x * ft) + fabsf(p.y * fp - t.y * ft)
              + fabsf(p.z * fp - t.z * ft) + fabsf(p.w * fp - t.w * ft);

    __shared__ float sh[8];
    int lane = threadIdx.x & 31, w = threadIdx.x >> 5;
    acc = warp_sum(acc);
    if (lane == 0) sh[w] = acc;
    __syncthreads();
    if (w == 0) {
        acc = (lane < 8) ? sh[lane] : 0.f;
        acc = warp_sum(acc);
        if (lane == 0) atomicAdd(&g_loss, (double)acc);
    }
}

__global__ void k_final(float* __restrict__ out) {
    double m = 0.0;
    #pragma unroll
    for (int i = 0; i < Bn; i++) m += g_sums[i][0];
    out[0] = (float)(g_loss / m);
}

extern "C" void kernel_launch(void* const* d_in, const int* in_sizes, int n_in,
                              void* d_out, int out_size) {
    const float* pred = (const float*)d_in[0];
    const float* targ = (const float*)d_in[1];
    const float* mask = (const float*)d_in[2];
    float* out = (float*)d_out;

    dim3 grid(GRIDX, Bn);
    k_init<<<1, 32>>>();
    k_pass1<<<grid, BLK>>>(pred, targ, mask);
    k_pass2<<<grid, BLK>>>();
    k_final<<<1, 1>>>(out);
}

// round 8
// speedup vs baseline: 1.0630x; 1.0630x over previous
#include <cuda_runtime.h>
#include <cuda_fp16.h>

// Problem geometry (fixed by the dataset)
constexpr int Bn = 16;
constexpr int Hh = 352;
constexpr int Ww = 1216;
constexpr int HW = Hh * Ww;          // 428032
constexpr int QPI = HW / 4;          // quads per image = 107008 = 418*256 exactly
constexpr int BLK = 256;
constexpr int GRIDX = QPI / BLK;     // 418
constexpr int NBLK2 = GRIDX * Bn;    // pass2 block count = 6688

// Scratch (allocation-free rule: __device__ globals). One 16B record per quad:
// {pc01, pc23, tc01, tc23} as packed fp16 pairs.
__device__ uint4    g_c[Bn * QPI];
__device__ double   g_sums[Bn][3];   // [img][0]=sum(mask) [1]=sum(m*|pc|) [2]=sum(m*|tc|)
__device__ double   g_loss;          // zero-init at module load; reset at end of each run
__device__ unsigned g_ticket;

__device__ __forceinline__ void sort3(float& a, float& b, float& c) {
    float t;
    t = fminf(a, b); b = fmaxf(a, b); a = t;
    t = fminf(a, c); c = fmaxf(a, c); a = t;
    t = fminf(b, c); c = fmaxf(b, c); b = t;
}
__device__ __forceinline__ float med3(float a, float b, float c) {
    return fmaxf(fminf(a, b), fminf(fmaxf(a, b), c));
}
__device__ __forceinline__ float max3(float a, float b, float c) { return fmaxf(a, fmaxf(b, c)); }
__device__ __forceinline__ float min3(float a, float b, float c) { return fminf(a, fminf(b, c)); }

__device__ __forceinline__ float warp_sum(float v) {
    #pragma unroll
    for (int o = 16; o; o >>= 1) v += __shfl_down_sync(0xffffffffu, v, o);
    return v;
}

// 4 horizontal contrasts (pixel - 3x3 zero-padded lower median) for one tensor.
// One tensor at a time keeps the live register set small (anti-spill).
__device__ __forceinline__ void contrast4(const float* __restrict__ base, int y, int x4,
                                          float out[4]) {
    float r[3][6];
    #pragma unroll
    for (int rr = 0; rr < 3; rr++) {
        int yy = y + rr - 1;
        if (yy < 0 || yy >= Hh) {
            #pragma unroll
            for (int c = 0; c < 6; c++) r[rr][c] = 0.f;
        } else {
            const float* row = base + yy * Ww;
            float4 v = *reinterpret_cast<const float4*>(row + x4);
            r[rr][1] = v.x; r[rr][2] = v.y; r[rr][3] = v.z; r[rr][4] = v.w;
            // edge scalars hit the same sectors as neighbor threads' float4 loads (L1 hits)
            r[rr][0] = (x4 > 0)      ? __ldg(row + x4 - 1) : 0.f;
            r[rr][5] = (x4 + 4 < Ww) ? __ldg(row + x4 + 4) : 0.f;
        }
    }
    float lo[6], mi[6], hi[6];
    #pragma unroll
    for (int c = 0; c < 6; c++) {
        float a = r[0][c], b = r[1][c], d = r[2][c];
        sort3(a, b, d); lo[c] = a; mi[c] = b; hi[c] = d;
    }
    #pragma unroll
    for (int i = 0; i < 4; i++) {
        float m = med3(max3(lo[i], lo[i+1], lo[i+2]),
                       med3(mi[i], mi[i+1], mi[i+2]),
                       min3(hi[i], hi[i+1], hi[i+2]));
        out[i] = r[1][i+1] - m;
    }
}

// pass1: contrasts -> fp16 scratch, per-image {sum m, sum m|pc|, sum m|tc|}.
__global__ __launch_bounds__(BLK) void k_pass1(const float* __restrict__ pred,
                                               const float* __restrict__ targ,
                                               const float* __restrict__ mask) {
    int img = blockIdx.y;
    int q   = blockIdx.x * BLK + threadIdx.x;   // < QPI (exact tiling)
    int y   = q / (Ww / 4);
    int x4  = (q % (Ww / 4)) * 4;
    int base = img * HW + y * Ww + x4;

    float pcs[4], tcs[4];
    contrast4(pred + img * HW, y, x4, pcs);
    contrast4(targ + img * HW, y, x4, tcs);

    __half2 pa = __floats2half2_rn(pcs[0], pcs[1]);
    __half2 pb = __floats2half2_rn(pcs[2], pcs[3]);
    __half2 ta = __floats2half2_rn(tcs[0], tcs[1]);
    __half2 tb = __floats2half2_rn(tcs[2], tcs[3]);
    uint4 rec;
    rec.x = *reinterpret_cast<unsigned*>(&pa);
    rec.y = *reinterpret_cast<unsigned*>(&pb);
    rec.z = *reinterpret_cast<unsigned*>(&ta);
    rec.w = *reinterpret_cast<unsigned*>(&tb);
    g_c[img * QPI + q] = rec;

    float4 mv = *reinterpret_cast<const float4*>(mask + base);
    float sm = mv.x + mv.y + mv.z + mv.w;
    float sp = mv.x * fabsf(pcs[0]) + mv.y * fabsf(pcs[1]) + mv.z * fabsf(pcs[2]) + mv.w * fabsf(pcs[3]);
    float st = mv.x * fabsf(tcs[0]) + mv.y * fabsf(tcs[1]) + mv.z * fabsf(tcs[2]) + mv.w * fabsf(tcs[3]);

    __shared__ float sh[8][3];
    int lane = threadIdx.x & 31, w = threadIdx.x >> 5;
    sm = warp_sum(sm); sp = warp_sum(sp); st = warp_sum(st);
    if (lane == 0) { sh[w][0] = sm; sh[w][1] = sp; sh[w][2] = st; }
    __syncthreads();
    if (w == 0) {
        sm = (lane < 8) ? sh[lane][0] : 0.f;
        sp = (lane < 8) ? sh[lane][1] : 0.f;
        st = (lane < 8) ? sh[lane][2] : 0.f;
        sm = warp_sum(sm); sp = warp_sum(sp); st = warp_sum(st);
        if (lane == 0) {
            atomicAdd(&g_sums[img][0], (double)sm);
            atomicAdd(&g_sums[img][1], (double)sp);
            atomicAdd(&g_sums[img][2], (double)st);
        }
    }
}

// pass2: stream fp16 contrasts, accumulate loss; last block finalizes + resets state.
__global__ __launch_bounds__(BLK) void k_pass2(float* __restrict__ out) {
    int img = blockIdx.y;
    int q   = blockIdx.x * BLK + threadIdx.x;

    double denom = g_sums[img][0];
    float fp = (float)(denom / g_sums[img][1]);   // 1/mean_pred
    float ft = (float)(denom / g_sums[img][2]);   // 1/mean_target

    uint4 rec = g_c[img * QPI + q];
    float2 p01 = __half22float2(*reinterpret_cast<__half2*>(&rec.x));
    float2 p23 = __half22float2(*reinterpret_cast<__half2*>(&rec.y));
    float2 t01 = __half22float2(*reinterpret_cast<__half2*>(&rec.z));
    float2 t23 = __half22float2(*reinterpret_cast<__half2*>(&rec.w));

    float acc = fabsf(p01.x * fp - t01.x * ft) + fabsf(p01.y * fp - t01.y * ft)
              + fabsf(p23.x * fp - t23.x * ft) + fabsf(p23.y * fp - t23.y * ft);

    __shared__ float sh[8];
    int lane = threadIdx.x & 31, w = threadIdx.x >> 5;
    acc = warp_sum(acc);
    if (lane == 0) sh[w] = acc;
    __syncthreads();
    if (w == 0) {
        acc = (lane < 8) ? sh[lane] : 0.f;
        acc = warp_sum(acc);
        if (lane == 0) atomicAdd(&g_loss, (double)acc);
    }
    // Completion ticket: the last block writes the output and resets all accumulators
    // so every graph replay starts from zeros (deterministic across replays).
    if (threadIdx.x == 0) {
        __threadfence();
        unsigned t = atomicAdd(&g_ticket, 1u);
        if (t == (unsigned)(NBLK2 - 1)) {
            double m = 0.0, lv = atomicAdd(&g_loss, 0.0);
            #pragma unroll
            for (int i = 0; i < Bn; i++) m += g_sums[i][0];
            out[0] = (float)(lv / m);
            #pragma unroll
            for (int i = 0; i < Bn; i++) {
                g_sums[i][0] = 0.0; g_sums[i][1] = 0.0; g_sums[i][2] = 0.0;
            }
            g_loss = 0.0;
            __threadfence();
            g_ticket = 0u;
        }
    }
}

extern "C" void kernel_launch(void* const* d_in, const int* in_sizes, int n_in,
                              void* d_out, int out_size) {
    const float* pred = (const float*)d_in[0];
    const float* targ = (const float*)d_in[1];
    const float* mask = (const float*)d_in[2];
    float* out = (float*)d_out;

    dim3 grid(GRIDX, Bn);
    k_pass1<<<grid, BLK>>>(pred, targ, mask);
    k_pass2<<<grid, BLK>>>(out);
}

// round 9
// speedup vs baseline: 1.6499x; 1.5521x over previous
#include <cuda_runtime.h>
#include <cuda_fp16.h>

// Problem geometry (fixed by the dataset)
constexpr int Bn = 16;
constexpr int Hh = 352;
constexpr int Ww = 1216;
constexpr int HW = Hh * Ww;          // 428032
constexpr int QPI = HW / 4;          // quads per image = 107008 = 418*256 exactly
constexpr int BLK = 256;
constexpr int GRIDX = QPI / BLK;     // 418
constexpr int NBLK1 = GRIDX * Bn;    // pass1 block count = 6688
constexpr int GRIDX2 = GRIDX / 2;    // 209  (each pass2 thread handles 2 quads)
constexpr int NBLK2 = GRIDX2 * Bn;   // pass2 block count = 3344
constexpr int STRIDE2 = GRIDX2 * BLK; // 53504 = QPI/2

// Scratch (allocation-free rule: __device__ globals). One 16B record per quad:
// {pc01, pc23, tc01, tc23} as packed fp16 pairs.
__device__ uint4    g_c[Bn * QPI];
__device__ double   g_sums[Bn][3];   // [img][0]=sum(mask) [1]=sum(m*|pc|) [2]=sum(m*|tc|)
__device__ float2   g_scale[Bn];     // {1/mean_pred, 1/mean_target} per image (pass1 epilogue)
__device__ double   g_loss;          // zero-init at module load; reset at end of each run
__device__ unsigned g_ticket1;
__device__ unsigned g_ticket2;

__device__ __forceinline__ void sort3(float& a, float& b, float& c) {
    float t;
    t = fminf(a, b); b = fmaxf(a, b); a = t;
    t = fminf(a, c); c = fmaxf(a, c); a = t;
    t = fminf(b, c); c = fmaxf(b, c); b = t;
}
__device__ __forceinline__ float med3(float a, float b, float c) {
    return fmaxf(fminf(a, b), fminf(fmaxf(a, b), c));
}
__device__ __forceinline__ float max3(float a, float b, float c) { return fmaxf(a, fmaxf(b, c)); }
__device__ __forceinline__ float min3(float a, float b, float c) { return fminf(a, fminf(b, c)); }

__device__ __forceinline__ float warp_sum(float v) {
    #pragma unroll
    for (int o = 16; o; o >>= 1) v += __shfl_down_sync(0xffffffffu, v, o);
    return v;
}

// 4 horizontal contrasts (pixel - 3x3 zero-padded lower median) for one tensor.
__device__ __forceinline__ void contrast4(const float* __restrict__ base, int y, int x4,
                                          float out[4]) {
    float r[3][6];
    #pragma unroll
    for (int rr = 0; rr < 3; rr++) {
        int yy = y + rr - 1;
        if (yy < 0 || yy >= Hh) {
            #pragma unroll
            for (int c = 0; c < 6; c++) r[rr][c] = 0.f;
        } else {
            const float* row = base + yy * Ww;
            float4 v = *reinterpret_cast<const float4*>(row + x4);
            r[rr][1] = v.x; r[rr][2] = v.y; r[rr][3] = v.z; r[rr][4] = v.w;
            r[rr][0] = (x4 > 0)      ? __ldg(row + x4 - 1) : 0.f;
            r[rr][5] = (x4 + 4 < Ww) ? __ldg(row + x4 + 4) : 0.f;
        }
    }
    float lo[6], mi[6], hi[6];
    #pragma unroll
    for (int c = 0; c < 6; c++) {
        float a = r[0][c], b = r[1][c], d = r[2][c];
        sort3(a, b, d); lo[c] = a; mi[c] = b; hi[c] = d;
    }
    #pragma unroll
    for (int i = 0; i < 4; i++) {
        float m = med3(max3(lo[i], lo[i+1], lo[i+2]),
                       med3(mi[i], mi[i+1], mi[i+2]),
                       min3(hi[i], hi[i+1], hi[i+2]));
        out[i] = r[1][i+1] - m;
    }
}

// pass1: contrasts -> fp16 scratch, per-image sums; LAST block precomputes the
// per-image float reciprocal-mean scales (all fp64 work lives here: 32 divides total).
__global__ __launch_bounds__(BLK) void k_pass1(const float* __restrict__ pred,
                                               const float* __restrict__ targ,
                                               const float* __restrict__ mask) {
    int img = blockIdx.y;
    int q   = blockIdx.x * BLK + threadIdx.x;   // < QPI (exact tiling)
    int y   = q / (Ww / 4);
    int x4  = (q % (Ww / 4)) * 4;
    int base = img * HW + y * Ww + x4;

    float pcs[4], tcs[4];
    contrast4(pred + img * HW, y, x4, pcs);
    contrast4(targ + img * HW, y, x4, tcs);

    __half2 pa = __floats2half2_rn(pcs[0], pcs[1]);
    __half2 pb = __floats2half2_rn(pcs[2], pcs[3]);
    __half2 ta = __floats2half2_rn(tcs[0], tcs[1]);
    __half2 tb = __floats2half2_rn(tcs[2], tcs[3]);
    uint4 rec;
    rec.x = *reinterpret_cast<unsigned*>(&pa);
    rec.y = *reinterpret_cast<unsigned*>(&pb);
    rec.z = *reinterpret_cast<unsigned*>(&ta);
    rec.w = *reinterpret_cast<unsigned*>(&tb);
    g_c[img * QPI + q] = rec;

    float4 mv = *reinterpret_cast<const float4*>(mask + base);
    float sm = mv.x + mv.y + mv.z + mv.w;
    float sp = mv.x * fabsf(pcs[0]) + mv.y * fabsf(pcs[1]) + mv.z * fabsf(pcs[2]) + mv.w * fabsf(pcs[3]);
    float st = mv.x * fabsf(tcs[0]) + mv.y * fabsf(tcs[1]) + mv.z * fabsf(tcs[2]) + mv.w * fabsf(tcs[3]);

    __shared__ float sh[8][3];
    int lane = threadIdx.x & 31, w = threadIdx.x >> 5;
    sm = warp_sum(sm); sp = warp_sum(sp); st = warp_sum(st);
    if (lane == 0) { sh[w][0] = sm; sh[w][1] = sp; sh[w][2] = st; }
    __syncthreads();
    if (w == 0) {
        sm = (lane < 8) ? sh[lane][0] : 0.f;
        sp = (lane < 8) ? sh[lane][1] : 0.f;
        st = (lane < 8) ? sh[lane][2] : 0.f;
        sm = warp_sum(sm); sp = warp_sum(sp); st = warp_sum(st);
        if (lane == 0) {
            atomicAdd(&g_sums[img][0], (double)sm);
            atomicAdd(&g_sums[img][1], (double)sp);
            atomicAdd(&g_sums[img][2], (double)st);
        }
    }
    // Epilogue: last pass1 block computes per-image scales (fp64 confined here).
    if (threadIdx.x == 0) {
        __threadfence();
        unsigned t = atomicAdd(&g_ticket1, 1u);
        if (t == (unsigned)(NBLK1 - 1)) {
            #pragma unroll
            for (int i = 0; i < Bn; i++) {
                double d = g_sums[i][0];
                g_scale[i] = make_float2((float)(d / g_sums[i][1]),
                                         (float)(d / g_sums[i][2]));
            }
            __threadfence();
            g_ticket1 = 0u;
        }
    }
}

// pass2: stream fp16 contrasts (2 records/thread), accumulate loss with float scales;
// last block finalizes + resets state for the next graph replay.
__global__ __launch_bounds__(BLK) void k_pass2(float* __restrict__ out) {
    int img = blockIdx.y;
    int q0  = blockIdx.x * BLK + threadIdx.x;

    float2 s = g_scale[img];          // broadcast load, no fp64 in this kernel's hot path
    float fp = s.x, ft = s.y;

    float acc = 0.f;
    #pragma unroll
    for (int it = 0; it < 2; it++) {
        uint4 rec = g_c[img * QPI + q0 + it * STRIDE2];
        float2 p01 = __half22float2(*reinterpret_cast<__half2*>(&rec.x));
        float2 p23 = __half22float2(*reinterpret_cast<__half2*>(&rec.y));
        float2 t01 = __half22float2(*reinterpret_cast<__half2*>(&rec.z));
        float2 t23 = __half22float2(*reinterpret_cast<__half2*>(&rec.w));
        acc += fabsf(p01.x * fp - t01.x * ft) + fabsf(p01.y * fp - t01.y * ft)
             + fabsf(p23.x * fp - t23.x * ft) + fabsf(p23.y * fp - t23.y * ft);
    }

    __shared__ float sh[8];
    int lane = threadIdx.x & 31, w = threadIdx.x >> 5;
    acc = warp_sum(acc);
    if (lane == 0) sh[w] = acc;
    __syncthreads();
    if (w == 0) {
        acc = (lane < 8) ? sh[lane] : 0.f;
        acc = warp_sum(acc);
        if (lane == 0) atomicAdd(&g_loss, (double)acc);
    }
    // Last block writes the output and resets accumulators (deterministic replays).
    if (threadIdx.x == 0) {
        __threadfence();
        unsigned t = atomicAdd(&g_ticket2, 1u);
        if (t == (unsigned)(NBLK2 - 1)) {
            double m = 0.0, lv = atomicAdd(&g_loss, 0.0);
            #pragma unroll
            for (int i = 0; i < Bn; i++) m += g_sums[i][0];
            out[0] = (float)(lv / m);
            #pragma unroll
            for (int i = 0; i < Bn; i++) {
                g_sums[i][0] = 0.0; g_sums[i][1] = 0.0; g_sums[i][2] = 0.0;
            }
            g_loss = 0.0;
            __threadfence();
            g_ticket2 = 0u;
        }
    }
}

extern "C" void kernel_launch(void* const* d_in, const int* in_sizes, int n_in,
                              void* d_out, int out_size) {
    const float* pred = (const float*)d_in[0];
    const float* targ = (const float*)d_in[1];
    const float* mask = (const float*)d_in[2];
    float* out = (float*)d_out;

    k_pass1<<<dim3(GRIDX, Bn), BLK>>>(pred, targ, mask);
    k_pass2<<<dim3(GRIDX2, Bn), BLK>>>(out);
}

// round 10
// speedup vs baseline: 1.6615x; 1.0070x over previous
#include <cuda_runtime.h>
#include <cuda_fp16.h>

// Problem geometry (fixed by the dataset)
constexpr int Bn = 16;
constexpr int Hh = 352;
constexpr int Ww = 1216;
constexpr int HW = Hh * Ww;            // 428032
constexpr int OPI = HW / 8;            // octets per image = 53504 = 209*256 exactly
constexpr int BLK = 256;
constexpr int GRIDX1 = OPI / BLK;      // 209
constexpr int NBLK1 = GRIDX1 * Bn;     // 3344
constexpr int GRIDX2 = 19;             // 53504 = 19*256*11 exactly
constexpr int ITER2 = 11;
constexpr int STRIDE2 = GRIDX2 * BLK;  // 4864
constexpr int NBLK2 = GRIDX2 * Bn;     // 304

// Scratch (allocation-free rule: __device__ globals). One uint4 = 8 fp16 contrasts.
__device__ uint4    g_pc[Bn * OPI];
__device__ uint4    g_tc[Bn * OPI];
__device__ double   g_sums[Bn][3];   // [img]{sum m, sum m|pc|, sum m|tc|}
__device__ float2   g_scale[Bn];     // {Σm/Σm|pc|, Σm/Σm|tc|} per image
__device__ double   g_loss;
__device__ unsigned g_ticket1;
__device__ unsigned g_ticket2;

__device__ __forceinline__ void sort3(float& a, float& b, float& c) {
    float t;
    t = fminf(a, b); b = fmaxf(a, b); a = t;
    t = fminf(a, c); c = fmaxf(a, c); a = t;
    t = fminf(b, c); c = fmaxf(b, c); b = t;
}
__device__ __forceinline__ float med3(float a, float b, float c) {
    return fmaxf(fminf(a, b), fminf(fmaxf(a, b), c));
}
__device__ __forceinline__ float max3(float a, float b, float c) { return fmaxf(a, fmaxf(b, c)); }
__device__ __forceinline__ float min3(float a, float b, float c) { return fminf(a, fminf(b, c)); }

__device__ __forceinline__ float warp_sum(float v) {
    #pragma unroll
    for (int o = 16; o; o >>= 1) v += __shfl_down_sync(0xffffffffu, v, o);
    return v;
}

// 8 horizontal contrasts (pixel - 3x3 zero-padded lower median) for one tensor.
__device__ __forceinline__ void contrast8(const float* __restrict__ base, int y, int x8,
                                          float out[8]) {
    float r[3][10];   // cols x8-1 .. x8+8
    #pragma unroll
    for (int rr = 0; rr < 3; rr++) {
        int yy = y + rr - 1;
        if (yy < 0 || yy >= Hh) {
            #pragma unroll
            for (int c = 0; c < 10; c++) r[rr][c] = 0.f;
        } else {
            const float* row = base + yy * Ww;
            float4 v0 = *reinterpret_cast<const float4*>(row + x8);
            float4 v1 = *reinterpret_cast<const float4*>(row + x8 + 4);
            r[rr][1] = v0.x; r[rr][2] = v0.y; r[rr][3] = v0.z; r[rr][4] = v0.w;
            r[rr][5] = v1.x; r[rr][6] = v1.y; r[rr][7] = v1.z; r[rr][8] = v1.w;
            r[rr][0] = (x8 > 0)      ? __ldg(row + x8 - 1) : 0.f;
            r[rr][9] = (x8 + 8 < Ww) ? __ldg(row + x8 + 8) : 0.f;
        }
    }
    float lo[10], mi[10], hi[10];
    #pragma unroll
    for (int c = 0; c < 10; c++) {
        float a = r[0][c], b = r[1][c], d = r[2][c];
        sort3(a, b, d); lo[c] = a; mi[c] = b; hi[c] = d;
    }
    #pragma unroll
    for (int i = 0; i < 8; i++) {
        float m = med3(max3(lo[i], lo[i+1], lo[i+2]),
                       med3(mi[i], mi[i+1], mi[i+2]),
                       min3(hi[i], hi[i+1], hi[i+2]));
        out[i] = r[1][i+1] - m;
    }
}

__device__ __forceinline__ uint4 pack8(const float c[8]) {
    __half2 h0 = __floats2half2_rn(c[0], c[1]);
    __half2 h1 = __floats2half2_rn(c[2], c[3]);
    __half2 h2 = __floats2half2_rn(c[4], c[5]);
    __half2 h3 = __floats2half2_rn(c[6], c[7]);
    uint4 r;
    r.x = *reinterpret_cast<unsigned*>(&h0);
    r.y = *reinterpret_cast<unsigned*>(&h1);
    r.z = *reinterpret_cast<unsigned*>(&h2);
    r.w = *reinterpret_cast<unsigned*>(&h3);
    return r;
}

// pass1: contrasts -> fp16 scratch, per-image sums; last block computes float scales
// (all fp64 divides confined to 32 total).
__global__ __launch_bounds__(BLK) void k_pass1(const float* __restrict__ pred,
                                               const float* __restrict__ targ,
                                               const float* __restrict__ mask) {
    int img = blockIdx.y;
    int q   = blockIdx.x * BLK + threadIdx.x;   // < OPI (exact tiling)
    int y   = q / (Ww / 8);
    int x8  = (q % (Ww / 8)) * 8;
    int base = img * HW + y * Ww + x8;

    float4 m0 = *reinterpret_cast<const float4*>(mask + base);
    float4 m1 = *reinterpret_cast<const float4*>(mask + base + 4);
    float mm[8] = {m0.x, m0.y, m0.z, m0.w, m1.x, m1.y, m1.z, m1.w};
    float sm = mm[0]+mm[1]+mm[2]+mm[3]+mm[4]+mm[5]+mm[6]+mm[7];

    // pred phase (packed & stored before targ phase to cap live registers)
    float cs[8];
    contrast8(pred + img * HW, y, x8, cs);
    float sp = 0.f;
    #pragma unroll
    for (int i = 0; i < 8; i++) sp += mm[i] * fabsf(cs[i]);
    g_pc[img * OPI + q] = pack8(cs);

    // targ phase
    contrast8(targ + img * HW, y, x8, cs);
    float st = 0.f;
    #pragma unroll
    for (int i = 0; i < 8; i++) st += mm[i] * fabsf(cs[i]);
    g_tc[img * OPI + q] = pack8(cs);

    __shared__ float sh[8][3];
    int lane = threadIdx.x & 31, w = threadIdx.x >> 5;
    sm = warp_sum(sm); sp = warp_sum(sp); st = warp_sum(st);
    if (lane == 0) { sh[w][0] = sm; sh[w][1] = sp; sh[w][2] = st; }
    __syncthreads();
    if (w == 0) {
        sm = (lane < 8) ? sh[lane][0] : 0.f;
        sp = (lane < 8) ? sh[lane][1] : 0.f;
        st = (lane < 8) ? sh[lane][2] : 0.f;
        sm = warp_sum(sm); sp = warp_sum(sp); st = warp_sum(st);
        if (lane == 0) {
            atomicAdd(&g_sums[img][0], (double)sm);
            atomicAdd(&g_sums[img][1], (double)sp);
            atomicAdd(&g_sums[img][2], (double)st);
        }
    }
    // Epilogue: last pass1 block computes per-image scales.
    if (threadIdx.x == 0) {
        __threadfence();
        unsigned t = atomicAdd(&g_ticket1, 1u);
        if (t == (unsigned)(NBLK1 - 1)) {
            #pragma unroll
            for (int i = 0; i < Bn; i++) {
                double d = g_sums[i][0];
                g_scale[i] = make_float2((float)(d / g_sums[i][1]),
                                         (float)(d / g_sums[i][2]));
            }
            __threadfence();
            g_ticket1 = 0u;
        }
    }
}

// pass2: stream fp16 contrasts (11 records/thread), float scales; last block
// finalizes the loss and resets state for the next graph replay.
__global__ __launch_bounds__(BLK) void k_pass2(float* __restrict__ out) {
    int img  = blockIdx.y;
    int idx0 = blockIdx.x * BLK + threadIdx.x;

    float2 s = g_scale[img];
    float fp = s.x, ft = s.y;

    float acc = 0.f;
    #pragma unroll 2
    for (int it = 0; it < ITER2; it++) {
        int q = img * OPI + idx0 + it * STRIDE2;
        uint4 rp = g_pc[q];
        uint4 rt = g_tc[q];
        const unsigned* up = &rp.x;
        const unsigned* ut = &rt.x;
        #pragma unroll
        for (int j = 0; j < 4; j++) {
            float2 p = __half22float2(*reinterpret_cast<const __half2*>(up + j));
            float2 t = __half22float2(*reinterpret_cast<const __half2*>(ut + j));
            acc += fabsf(p.x * fp - t.x * ft) + fabsf(p.y * fp - t.y * ft);
        }
    }

    __shared__ float sh[8];
    int lane = threadIdx.x & 31, w = threadIdx.x >> 5;
    acc = warp_sum(acc);
    if (lane == 0) sh[w] = acc;
    __syncthreads();
    if (w == 0) {
        acc = (lane < 8) ? sh[lane] : 0.f;
        acc = warp_sum(acc);
        if (lane == 0) atomicAdd(&g_loss, (double)acc);
    }
    // Last block writes the output and resets accumulators (deterministic replays).
    if (threadIdx.x == 0) {
        __threadfence();
        unsigned t = atomicAdd(&g_ticket2, 1u);
        if (t == (unsigned)(NBLK2 - 1)) {
            double m = 0.0, lv = atomicAdd(&g_loss, 0.0);
            #pragma unroll
            for (int i = 0; i < Bn; i++) m += g_sums[i][0];
            out[0] = (float)(lv / m);
            #pragma unroll
            for (int i = 0; i < Bn; i++) {
                g_sums[i][0] = 0.0; g_sums[i][1] = 0.0; g_sums[i][2] = 0.0;
            }
            g_loss = 0.0;
            __threadfence();
            g_ticket2 = 0u;
        }
    }
}

extern "C" void kernel_launch(void* const* d_in, const int* in_sizes, int n_in,
                              void* d_out, int out_size) {
    const float* pred = (const float*)d_in[0];
    const float* targ = (const float*)d_in[1];
    const float* mask = (const float*)d_in[2];
    float* out = (float*)d_out;

    k_pass1<<<dim3(GRIDX1, Bn), BLK>>>(pred, targ, mask);
    k_pass2<<<dim3(GRIDX2, Bn), BLK>>>(out);
}

// round 13
// speedup vs baseline: 1.8288x; 1.1007x over previous
#include <cuda_runtime.h>
#include <cuda_fp16.h>

// Problem geometry (fixed by the dataset)
constexpr int Bn = 16;
constexpr int Hh = 352;
constexpr int Ww = 1216;
constexpr int HW = Hh * Ww;           // 428032
constexpr int XQ = Ww / 4;            // 304 x4-positions per row
constexpr int SROWS = 11;             // rows per vertical strip
constexpr int NSTRIP = Hh / SROWS;    // 32
constexpr int TPI = XQ * NSTRIP;      // 9728 threads per image
constexpr int BLK = 256;
constexpr int GRIDX1 = TPI / BLK;     // 38 (exact)
constexpr int NBLK1 = GRIDX1 * Bn;    // 608
constexpr int NQ4 = HW / 4;           // 107008 quads per image
constexpr int OPI8 = HW / 8;          // 53504 octets per image
constexpr int TOT8 = Bn * OPI8;       // 856064
constexpr int ITER2 = 4;
constexpr int GRIDX2 = TOT8 / (BLK * ITER2);  // 836 (exact)
constexpr int STRIDE2 = GRIDX2 * BLK;         // 214016 = exactly 4 images of octets

// Scratch (allocation-free: __device__ globals). fp16 contrasts.
// Written as uint2 per 4px by pass1; read as uint4 (8px) by pass2.
__device__ uint4    g_pc[TOT8];
__device__ uint4    g_tc[TOT8];
__device__ double   g_sums[Bn][3];   // [img]{sum m, sum m|pc|, sum m|tc|}
__device__ float2   g_scale[Bn];     // {Σm/Σm|pc|, Σm/Σm|tc|} per image
__device__ double   g_loss;
__device__ unsigned g_ticket1;
__device__ unsigned g_ticket2;

__device__ __forceinline__ void sort3(float& a, float& b, float& c) {
    float t;
    t = fminf(a, b); b = fmaxf(a, b); a = t;
    t = fminf(a, c); c = fmaxf(a, c); a = t;
    t = fminf(b, c); c = fmaxf(b, c); b = t;
}
__device__ __forceinline__ float med3(float a, float b, float c) {
    return fmaxf(fminf(a, b), fminf(fmaxf(a, b), c));
}
__device__ __forceinline__ float max3(float a, float b, float c) { return fmaxf(a, fmaxf(b, c)); }
__device__ __forceinline__ float min3(float a, float b, float c) { return fminf(a, fminf(b, c)); }

__device__ __forceinline__ float warp_sum(float v) {
    #pragma unroll
    for (int o = 16; o; o >>= 1) v += __shfl_down_sync(0xffffffffu, v, o);
    return v;
}

__device__ __forceinline__ void zero6(float v[6]) {
    #pragma unroll
    for (int i = 0; i < 6; i++) v[i] = 0.f;
}
__device__ __forceinline__ void load6(const float* __restrict__ row, int x4, float v[6]) {
    const float* p = row + x4 * 4;
    float4 f = *reinterpret_cast<const float4*>(p);
    v[1] = f.x; v[2] = f.y; v[3] = f.z; v[4] = f.w;
    v[0] = (x4 > 0)      ? __ldg(p - 1) : 0.f;     // L1 hits (neighbor threads' sectors)
    v[5] = (x4 < XQ - 1) ? __ldg(p + 4) : 0.f;
}

// One tensor over an 11-row strip at column window x4 (rolling 3-row register
// window: each row costs ONE new row load). Stores fp16 contrasts, returns
// sum(mask*|contrast|); optionally accumulates sum(mask) into *smAcc.
template <bool ACC_MASK>
__device__ __forceinline__ float strip_tensor(const float* __restrict__ tb,
                                              const float* __restrict__ mb,
                                              int y0, int x4,
                                              uint2* __restrict__ outp,
                                              float* smAcc) {
    float a[6], b[6], c[6];
    if (y0 > 0) load6(tb + (y0 - 1) * Ww, x4, a); else zero6(a);
    load6(tb + y0 * Ww, x4, b);

    float wsum = 0.f;
    #pragma unroll 1
    for (int r = 0; r < SROWS; r++) {
        int y = y0 + r;
        if (y + 1 < Hh) load6(tb + (y + 1) * Ww, x4, c); else zero6(c);

        float lo[6], mi[6], hi[6];
        #pragma unroll
        for (int i = 0; i < 6; i++) {
            float u = a[i], v = b[i], w = c[i];
            sort3(u, v, w); lo[i] = u; mi[i] = v; hi[i] = w;
        }
        float cs[4];
        #pragma unroll
        for (int i = 0; i < 4; i++) {
            float m = med3(max3(lo[i], lo[i+1], lo[i+2]),
                           med3(mi[i], mi[i+1], mi[i+2]),
                           min3(hi[i], hi[i+1], hi[i+2]));
            cs[i] = b[i + 1] - m;
        }

        float4 m4 = *reinterpret_cast<const float4*>(mb + y * Ww + x4 * 4);
        wsum += m4.x * fabsf(cs[0]) + m4.y * fabsf(cs[1])
              + m4.z * fabsf(cs[2]) + m4.w * fabsf(cs[3]);
        if (ACC_MASK) *smAcc += m4.x + m4.y + m4.z + m4.w;

        __half2 h0 = __floats2half2_rn(cs[0], cs[1]);
        __half2 h1 = __floats2half2_rn(cs[2], cs[3]);
        uint2 rec;
        rec.x = *reinterpret_cast<unsigned*>(&h0);
        rec.y = *reinterpret_cast<unsigned*>(&h1);
        outp[y * XQ] = rec;

        #pragma unroll
        for (int i = 0; i < 6; i++) { a[i] = b[i]; b[i] = c[i]; }
    }
    return wsum;
}

// pass1: contrasts -> fp16 scratch, per-image sums; last block computes float scales.
__global__ __launch_bounds__(BLK) void k_pass1(const float* __restrict__ pred,
                                               const float* __restrict__ targ,
                                               const float* __restrict__ mask) {
    int img = blockIdx.y;
    int t   = blockIdx.x * BLK + threadIdx.x;   // < TPI (exact)
    int x4    = t % XQ;
    int strip = t / XQ;
    int y0    = strip * SROWS;

    const float* mb = mask + img * HW;
    uint2* pp = reinterpret_cast<uint2*>(g_pc) + img * NQ4 + x4;
    uint2* tp = reinterpret_cast<uint2*>(g_tc) + img * NQ4 + x4;

    float sm = 0.f;
    float sp = strip_tensor<true >(pred + img * HW, mb, y0, x4, pp, &sm);
    float st = strip_tensor<false>(targ + img * HW, mb, y0, x4, tp, &sm);

    __shared__ float sh[8][3];
    int lane = threadIdx.x & 31, w = threadIdx.x >> 5;
    sm = warp_sum(sm); sp = warp_sum(sp); st = warp_sum(st);
    if (lane == 0) { sh[w][0] = sm; sh[w][1] = sp; sh[w][2] = st; }
    __syncthreads();
    if (w == 0) {
        sm = (lane < 8) ? sh[lane][0] : 0.f;
        sp = (lane < 8) ? sh[lane][1] : 0.f;
        st = (lane < 8) ? sh[lane][2] : 0.f;
        sm = warp_sum(sm); sp = warp_sum(sp); st = warp_sum(st);
        if (lane == 0) {
            atomicAdd(&g_sums[img][0], (double)sm);
            atomicAdd(&g_sums[img][1], (double)sp);
            atomicAdd(&g_sums[img][2], (double)st);
        }
    }
    // Epilogue: last pass1 block computes per-image scales (fp64 confined: 32 divides).
    if (threadIdx.x == 0) {
        __threadfence();
        unsigned tk = atomicAdd(&g_ticket1, 1u);
        if (tk == (unsigned)(NBLK1 - 1)) {
            #pragma unroll
            for (int i = 0; i < Bn; i++) {
                double d = g_sums[i][0];
                g_scale[i] = make_float2((float)(d / g_sums[i][1]),
                                         (float)(d / g_sums[i][2]));
            }
            __threadfence();
            g_ticket1 = 0u;
        }
    }
}

// pass2: stream fp16 contrasts (4 octets/thread; stride = exactly 4 images so the
// within-image remainder is loop-invariant). Last block finalizes + resets.
__global__ __launch_bounds__(BLK) void k_pass2(float* __restrict__ out) {
    int idx0 = blockIdx.x * BLK + threadIdx.x;   // [0, STRIDE2)
    int img0 = idx0 / OPI8;                      // in [0, 4)
    int rem  = idx0 % OPI8;

    float acc = 0.f;
    #pragma unroll
    for (int it = 0; it < ITER2; it++) {
        int img = img0 + 4 * it;
        float2 s = g_scale[img];
        float fp = s.x, ft = s.y;
        int q = img * OPI8 + rem;
        uint4 rp = g_pc[q];
        uint4 rt = g_tc[q];
        const unsigned* up = &rp.x;
        const unsigned* ut = &rt.x;
        #pragma unroll
        for (int j = 0; j < 4; j++) {
            float2 p = __half22float2(*reinterpret_cast<const __half2*>(up + j));
            float2 tt = __half22float2(*reinterpret_cast<const __half2*>(ut + j));
            acc += fabsf(p.x * fp - tt.x * ft) + fabsf(p.y * fp - tt.y * ft);
        }
    }

    __shared__ float sh[8];
    int lane = threadIdx.x & 31, w = threadIdx.x >> 5;
    acc = warp_sum(acc);
    if (lane == 0) sh[w] = acc;
    __syncthreads();
    if (w == 0) {
        acc = (lane < 8) ? sh[lane] : 0.f;
        acc = warp_sum(acc);
        if (lane == 0) atomicAdd(&g_loss, (double)acc);
    }
    // Last block writes the output and resets accumulators (deterministic replays).
    if (threadIdx.x == 0) {
        __threadfence();
        unsigned tk = atomicAdd(&g_ticket2, 1u);
        if (tk == (unsigned)(GRIDX2 - 1)) {
            double m = 0.0, lv = atomicAdd(&g_loss, 0.0);
            #pragma unroll
            for (int i = 0; i < Bn; i++) m += g_sums[i][0];
            out[0] = (float)(lv / m);
            #pragma unroll
            for (int i = 0; i < Bn; i++) {
                g_sums[i][0] = 0.0; g_sums[i][1] = 0.0; g_sums[i][2] = 0.0;
            }
            g_loss = 0.0;
            __threadfence();
            g_ticket2 = 0u;
        }
    }
}

extern "C" void kernel_launch(void* const* d_in, const int* in_sizes, int n_in,
                              void* d_out, int out_size) {
    const float* pred = (const float*)d_in[0];
    const float* targ = (const float*)d_in[1];
    const float* mask = (const float*)d_in[2];
    float* out = (float*)d_out;

    k_pass1<<<dim3(GRIDX1, Bn), BLK>>>(pred, targ, mask);
    k_pass2<<<GRIDX2, BLK>>>(out);
}

// round 15
// speedup vs baseline: 1.8375x; 1.0048x over previous
#include <cuda_runtime.h>
#include <cuda_fp16.h>

// Problem geometry (fixed by the dataset)
constexpr int Bn = 16;
constexpr int Hh = 352;
constexpr int Ww = 1216;
constexpr int HW = Hh * Ww;           // 428032
constexpr int XQ = Ww / 4;            // 304 x4-positions per row
constexpr int SROWS = 11;             // rows per vertical strip
constexpr int NSTRIP = Hh / SROWS;    // 32
constexpr int TPI = XQ * NSTRIP;      // 9728 threads per image
constexpr int BLK = 256;
constexpr int GRIDX1 = TPI / BLK;     // 38 (exact)
constexpr int NBLK1 = GRIDX1 * Bn;    // 608
constexpr int NQ4 = HW / 4;           // 107008 quad-records per image
constexpr int ITER2 = 2;
constexpr int GRIDX2 = NQ4 / (BLK * ITER2);   // 209 (exact)
constexpr int STRIDE2 = GRIDX2 * BLK;         // 53504 = NQ4/2
constexpr int NBLK2 = GRIDX2 * Bn;            // 3344

// Scratch (allocation-free: __device__ globals).
// One uint4 per 4 pixels: {pc01, pc23, tc01, tc23} packed fp16.
__device__ uint4    g_c[Bn * NQ4];
__device__ double   g_sums[Bn][3];   // [img]{sum m, sum m|pc|, sum m|tc|}
__device__ float2   g_scale[Bn];     // {Σm/Σm|pc|, Σm/Σm|tc|} per image
__device__ double   g_loss;
__device__ unsigned g_ticket1;
__device__ unsigned g_ticket2;

__device__ __forceinline__ void sort3(float& a, float& b, float& c) {
    float t;
    t = fminf(a, b); b = fmaxf(a, b); a = t;
    t = fminf(a, c); c = fmaxf(a, c); a = t;
    t = fminf(b, c); c = fmaxf(b, c); b = t;
}
__device__ __forceinline__ float med3(float a, float b, float c) {
    return fmaxf(fminf(a, b), fminf(fmaxf(a, b), c));
}
__device__ __forceinline__ float max3(float a, float b, float c) { return fmaxf(a, fmaxf(b, c)); }
__device__ __forceinline__ float min3(float a, float b, float c) { return fminf(a, fminf(b, c)); }

__device__ __forceinline__ float warp_sum(float v) {
    #pragma unroll
    for (int o = 16; o; o >>= 1) v += __shfl_down_sync(0xffffffffu, v, o);
    return v;
}

__device__ __forceinline__ void zero6(float v[6]) {
    #pragma unroll
    for (int i = 0; i < 6; i++) v[i] = 0.f;
}
__device__ __forceinline__ void load6(const float* __restrict__ row, int x4, float v[6]) {
    const float* p = row + x4 * 4;
    float4 f = *reinterpret_cast<const float4*>(p);
    v[1] = f.x; v[2] = f.y; v[3] = f.z; v[4] = f.w;
    v[0] = (x4 > 0)      ? __ldg(p - 1) : 0.f;     // neighbor threads' sectors: L1 hits
    v[5] = (x4 < XQ - 1) ? __ldg(p + 4) : 0.f;
}

// 4 medians-of-9 from a 3x6 window held as rows a,b,c; cs[i] = center - median9.
__device__ __forceinline__ void med4(const float a[6], const float b[6], const float c[6],
                                     float cs[4]) {
    float lo[6], mi[6], hi[6];
    #pragma unroll
    for (int i = 0; i < 6; i++) {
        float u = a[i], v = b[i], w = c[i];
        sort3(u, v, w); lo[i] = u; mi[i] = v; hi[i] = w;
    }
    #pragma unroll
    for (int i = 0; i < 4; i++) {
        float m = med3(max3(lo[i], lo[i+1], lo[i+2]),
                       med3(mi[i], mi[i+1], mi[i+2]),
                       min3(hi[i], hi[i+1], hi[i+2]));
        cs[i] = b[i + 1] - m;
    }
}

// pass1: both tensors fused in one rolling-window strip loop (3 independent row
// loads per iteration -> high MLP; one mask load per row). Stores interleaved
// fp16 contrast records; per-image sums via block reduce + atomics; last block
// computes the per-image float scales (all fp64 confined to 32 divides).
__global__ __launch_bounds__(BLK) void k_pass1(const float* __restrict__ pred,
                                               const float* __restrict__ targ,
                                               const float* __restrict__ mask) {
    int img = blockIdx.y;
    int t   = blockIdx.x * BLK + threadIdx.x;   // < TPI (exact)
    int x4    = t % XQ;
    int strip = t / XQ;
    int y0    = strip * SROWS;

    const float* pb = pred + img * HW;
    const float* tb = targ + img * HW;
    const float* mb = mask + img * HW;
    uint4* outp = g_c + img * NQ4 + x4;

    float A0[6], B0[6], C0[6], A1[6], B1[6], C1[6];
    if (y0 > 0) {
        load6(pb + (y0 - 1) * Ww, x4, A0);
        load6(tb + (y0 - 1) * Ww, x4, A1);
    } else { zero6(A0); zero6(A1); }
    load6(pb + y0 * Ww, x4, B0);
    load6(tb + y0 * Ww, x4, B1);

    float sm = 0.f, sp = 0.f, st = 0.f;
    #pragma unroll 2
    for (int r = 0; r < SROWS; r++) {
        int y = y0 + r;
        // Next-row loads first: 2 independent float4 + edges, overlappable with compute.
        if (y + 1 < Hh) {
            load6(pb + (y + 1) * Ww, x4, C0);
            load6(tb + (y + 1) * Ww, x4, C1);
        } else { zero6(C0); zero6(C1); }
        float4 m4 = *reinterpret_cast<const float4*>(mb + y * Ww + x4 * 4);

        float p4[4], t4[4];
        med4(A0, B0, C0, p4);
        med4(A1, B1, C1, t4);

        sm += m4.x + m4.y + m4.z + m4.w;
        sp += m4.x * fabsf(p4[0]) + m4.y * fabsf(p4[1]) + m4.z * fabsf(p4[2]) + m4.w * fabsf(p4[3]);
        st += m4.x * fabsf(t4[0]) + m4.y * fabsf(t4[1]) + m4.z * fabsf(t4[2]) + m4.w * fabsf(t4[3]);

        __half2 h0 = __floats2half2_rn(p4[0], p4[1]);
        __half2 h1 = __floats2half2_rn(p4[2], p4[3]);
        __half2 h2 = __floats2half2_rn(t4[0], t4[1]);
        __half2 h3 = __floats2half2_rn(t4[2], t4[3]);
        uint4 rec;
        rec.x = *reinterpret_cast<unsigned*>(&h0);
        rec.y = *reinterpret_cast<unsigned*>(&h1);
        rec.z = *reinterpret_cast<unsigned*>(&h2);
        rec.w = *reinterpret_cast<unsigned*>(&h3);
        outp[y * XQ] = rec;

        #pragma unroll
        for (int i = 0; i < 6; i++) {
            A0[i] = B0[i]; B0[i] = C0[i];
            A1[i] = B1[i]; B1[i] = C1[i];
        }
    }

    __shared__ float sh[8][3];
    int lane = threadIdx.x & 31, w = threadIdx.x >> 5;
    sm = warp_sum(sm); sp = warp_sum(sp); st = warp_sum(st);
    if (lane == 0) { sh[w][0] = sm; sh[w][1] = sp; sh[w][2] = st; }
    __syncthreads();
    if (w == 0) {
        sm = (lane < 8) ? sh[lane][0] : 0.f;
        sp = (lane < 8) ? sh[lane][1] : 0.f;
        st = (lane < 8) ? sh[lane][2] : 0.f;
        sm = warp_sum(sm); sp = warp_sum(sp); st = warp_sum(st);
        if (lane == 0) {
            atomicAdd(&g_sums[img][0], (double)sm);
            atomicAdd(&g_sums[img][1], (double)sp);
            atomicAdd(&g_sums[img][2], (double)st);
        }
    }
    // Epilogue: last pass1 block computes per-image scales.
    if (threadIdx.x == 0) {
        __threadfence();
        unsigned tk = atomicAdd(&g_ticket1, 1u);
        if (tk == (unsigned)(NBLK1 - 1)) {
            #pragma unroll
            for (int i = 0; i < Bn; i++) {
                double d = g_sums[i][0];
                g_scale[i] = make_float2((float)(d / g_sums[i][1]),
                                         (float)(d / g_sums[i][2]));
            }
            __threadfence();
            g_ticket1 = 0u;
        }
    }
}

// pass2: one LDG.128 per 4 pixels (interleaved record), 2 records/thread.
// Last block finalizes the loss and resets state for the next graph replay.
__global__ __launch_bounds__(BLK) void k_pass2(float* __restrict__ out) {
    int img = blockIdx.y;
    int i0  = blockIdx.x * BLK + threadIdx.x;

    float2 s = g_scale[img];
    float fp = s.x, ft = s.y;

    float acc = 0.f;
    #pragma unroll
    for (int it = 0; it < ITER2; it++) {
        uint4 rec = g_c[img * NQ4 + i0 + it * STRIDE2];
        float2 p01 = __half22float2(*reinterpret_cast<__half2*>(&rec.x));
        float2 p23 = __half22float2(*reinterpret_cast<__half2*>(&rec.y));
        float2 t01 = __half22float2(*reinterpret_cast<__half2*>(&rec.z));
        float2 t23 = __half22float2(*reinterpret_cast<__half2*>(&rec.w));
        acc += fabsf(p01.x * fp - t01.x * ft) + fabsf(p01.y * fp - t01.y * ft)
             + fabsf(p23.x * fp - t23.x * ft) + fabsf(p23.y * fp - t23.y * ft);
    }

    __shared__ float sh[8];
    int lane = threadIdx.x & 31, w = threadIdx.x >> 5;
    acc = warp_sum(acc);
    if (lane == 0) sh[w] = acc;
    __syncthreads();
    if (w == 0) {
        acc = (lane < 8) ? sh[lane] : 0.f;
        acc = warp_sum(acc);
        if (lane == 0) atomicAdd(&g_loss, (double)acc);
    }
    // Last block writes the output and resets accumulators (deterministic replays).
    if (threadIdx.x == 0) {
        __threadfence();
        unsigned tk = atomicAdd(&g_ticket2, 1u);
        if (tk == (unsigned)(NBLK2 - 1)) {
            double m = 0.0, lv = atomicAdd(&g_loss, 0.0);
            #pragma unroll
            for (int i = 0; i < Bn; i++) m += g_sums[i][0];
            out[0] = (float)(lv / m);
            #pragma unroll
            for (int i = 0; i < Bn; i++) {
                g_sums[i][0] = 0.0; g_sums[i][1] = 0.0; g_sums[i][2] = 0.0;
            }
            g_loss = 0.0;
            __threadfence();
            g_ticket2 = 0u;
        }
    }
}

extern "C" void kernel_launch(void* const* d_in, const int* in_sizes, int n_in,
                              void* d_out, int out_size) {
    const float* pred = (const float*)d_in[0];
    const float* targ = (const float*)d_in[1];
    const float* mask = (const float*)d_in[2];
    float* out = (float*)d_out;

    k_pass1<<<dim3(GRIDX1, Bn), BLK>>>(pred, targ, mask);
    k_pass2<<<dim3(GRIDX2, Bn), BLK>>>(out);
}